// round 13
// baseline (speedup 1.0000x reference)
#include <cuda_runtime.h>
#include <cuda_bf16.h>

#define BSEQ 512
#define LSEQ 512
#define AA   20
#define CCH  8
#define NREST 8
#define PA   24      // xTp pitch (bf16): 48B rows -> conflict-free ldmatrix.trans
#define PW   264     // W smem pitch (bf16): 528B rows -> conflict-free ldmatrix

#define LDSM_X4_T(R, addr) \
    asm volatile("ldmatrix.sync.aligned.m8n8.x4.trans.shared.b16 " \
                 "{%0,%1,%2,%3}, [%4];" \
                 : "=r"((R)[0]), "=r"((R)[1]), "=r"((R)[2]), "=r"((R)[3]) \
                 : "r"(addr))
#define LDSM_X2(R, addr) \
    asm volatile("ldmatrix.sync.aligned.m8n8.x2.shared.b16 {%0,%1}, [%2];" \
                 : "=r"((R)[0]), "=r"((R)[1]) : "r"(addr))
#define MMA_BF16(C, A, B) \
    asm volatile("mma.sync.aligned.m16n8k16.row.col.f32.bf16.bf16.f32 " \
                 "{%0,%1,%2,%3}, {%4,%5,%6,%7}, {%8,%9}, {%0,%1,%2,%3};" \
                 : "+f"((C)[0]), "+f"((C)[1]), "+f"((C)[2]), "+f"((C)[3]) \
                 : "r"((A)[0]), "r"((A)[1]), "r"((A)[2]), "r"((A)[3]), \
                   "r"((B)[0]), "r"((B)[1]))
#define CP_ASYNC16(smem_u32, gptr) \
    asm volatile("cp.async.cg.shared.global [%0], [%1], 16;" \
                 :: "r"(smem_u32), "l"(gptr))
#define CP_COMMIT() asm volatile("cp.async.commit_group;")
#define CP_WAIT0()  asm volatile("cp.async.wait_group 0;")

// Precomputed: W_eff split into bf16 hi/lo pairs, and U = I + V.
__device__ __nv_bfloat16 g_Whi[CCH][LSEQ];
__device__ __nv_bfloat16 g_Wlo[CCH][LSEQ];
__device__ float g_U[AA * AA];

// ---------------------------------------------------------------------------
// Precompute kernel (primary, PDL trigger at entry). Blocks 0..7 -> one W_eff
// channel via the conv+pool adjoint, emitted as bf16 hi/lo; block 8 -> U;
// blocks 9..168 -> zero out.
// ---------------------------------------------------------------------------
template<int LEN2>
__device__ __forceinline__ void adj_layer(const float (*cur)[256],
                                          float (*nxt)[256],
                                          const float* __restrict__ w) {
    for (int idx = threadIdx.x; idx < CCH * LEN2; idx += 256) {
        const int i = idx / LEN2;
        const int p = idx % LEN2;
        float acc = 0.f;
        #pragma unroll
        for (int o = 0; o < CCH; ++o) {
            #pragma unroll
            for (int k = 0; k < 3; ++k) {
                const int q = p - k + 1;
                if (q >= 0 && q < LEN2)
                    acc += w[(o * CCH + i) * 3 + k] * 0.5f * cur[o][q >> 1];
            }
        }
        nxt[i][p] = acc;
    }
    __syncthreads();
}

__global__ void __launch_bounds__(256)
precompute_kernel(const float* __restrict__ lpm,
                  const float* __restrict__ pm,
                  const float* __restrict__ w_first,
                  const float* __restrict__ w_rest,
                  float* __restrict__ out) {
#if __CUDA_ARCH__ >= 900
    cudaTriggerProgrammaticLaunchCompletion();
#endif
    const int blk = blockIdx.x;
    const int tid = threadIdx.x;

    if (blk < CCH) {
        __shared__ float bufA[CCH][256];
        __shared__ float bufB[CCH][256];
        __shared__ float wsh[NREST * CCH * CCH * 3];

        for (int i = tid; i < NREST * CCH * CCH * 3; i += 256)
            wsh[i] = w_rest[i];
        if (tid < CCH) bufA[tid][0] = (tid == blk) ? 1.f : 0.f;
        __syncthreads();

        float (*cur)[256] = bufA;
        float (*nxt)[256] = bufB;
        float (*tmp)[256];
        #define STEP(L2, LI) \
            adj_layer<L2>(cur, nxt, wsh + (LI) * 192); \
            tmp = cur; cur = nxt; nxt = tmp;
        STEP(2, 7)  STEP(4, 6)  STEP(8, 5)   STEP(16, 4)
        STEP(32, 3) STEP(64, 2) STEP(128, 1) STEP(256, 0)
        #undef STEP

        for (int p = tid; p < LSEQ; p += 256) {
            float acc = 0.f;
            #pragma unroll
            for (int o = 0; o < CCH; ++o) {
                #pragma unroll
                for (int k = 0; k < 3; ++k) {
                    const int q = p - k + 1;
                    if (q >= 0 && q < LSEQ)
                        acc += w_first[o * 3 + k] * 0.5f * cur[o][q >> 1];
                }
            }
            const __nv_bfloat16 hi = __float2bfloat16(acc);
            g_Whi[blk][p] = hi;
            g_Wlo[blk][p] = __float2bfloat16(acc - __bfloat162float(hi));
        }
    } else if (blk == CCH) {
        // U[a][i] = delta(a,i) + V[a][i]
        for (int idx = tid; idx < AA * AA; idx += 256) {
            const int a = idx / AA, i = idx % AA;
            float v = (a == i) ? 1.f : 0.f;
            if (i != a && i != AA - 1) {
                const int r = (a < i) ? a : i;
                const int c = (a < i) ? i : a;
                float l = lpm[r * AA + c];
                l = fminf(fmaxf(l, 1e-3f), 1.f);
                v = l * pm[r * AA + c];
            }
            g_U[idx] = v;
        }
    } else {
        const int z = blk - (CCH + 1);          // 0..159
        if (tid < 128)
            reinterpret_cast<float4*>(out)[z * 128 + tid] =
                make_float4(0.f, 0.f, 0.f, 0.f);
    }
}

// ---------------------------------------------------------------------------
// Main kernel (secondary, PDL): grid 1024 = 512 sequences x 2 halves.
// Pipeline per block: issue cp.async for the 20KB x chunk -> gridsync (cp
// flight hides under the precompute wait) -> stage W -> cp wait -> smem
// convert/transpose fp32->bf16 -> tensor-core GEMM -> reduce -> U epilogue.
// Dp/g_sh alias the dead fp32 staging buffer to keep 5 blocks/SM.
// ---------------------------------------------------------------------------
__global__ void __launch_bounds__(256, 5)
main_kernel(const float* __restrict__ x, float* __restrict__ out) {
    __shared__ __align__(16) char nat_raw[256 * AA * 4];    // 20480 B (aliased)
    __shared__ __nv_bfloat16 xTp[256 * PA + 32];            // 12352 B
    __shared__ __nv_bfloat16 Whi_sh[CCH * PW];              //  4224 B
    __shared__ __nv_bfloat16 Wlo_sh[CCH * PW];              //  4224 B

    float* nat = reinterpret_cast<float*>(nat_raw);
    float (*Dp)[32][8] = reinterpret_cast<float (*)[32][8]>(nat_raw);   // 8192 B
    float (*g_sh)[CCH] = reinterpret_cast<float (*)[CCH]>(nat_raw + 8192);

    const int bi   = blockIdx.x;
    const int b    = bi >> 1;
    const int half = bi & 1;
    const int tid  = threadIdx.x;
    const int lane = tid & 31;
    const int w    = tid >> 5;

    // ---- Issue the 20KB x chunk as cp.async (register-free, max MLP) -------
    {
        const unsigned nb =
            (unsigned)__cvta_generic_to_shared(nat) + (unsigned)tid * 16u;
        const char* xg = reinterpret_cast<const char*>(x)
                       + (size_t)b * 40960 + half * 20480 + (size_t)tid * 16;
        #pragma unroll
        for (int it = 0; it < 5; ++it)
            CP_ASYNC16(nb + it * 4096u, xg + it * 4096);
        CP_COMMIT();
    }

    // ---- Wait for precompute; the cp.async flight hides under this ---------
#if __CUDA_ARCH__ >= 900
    cudaGridDependencySynchronize();
#endif

    // ---- Stage W hi/lo (L2-hot) --------------------------------------------
    {
        const uint4* Hg = reinterpret_cast<const uint4*>(g_Whi);
        const uint4* Lg = reinterpret_cast<const uint4*>(g_Wlo);
        const int c = tid >> 5, q = tid & 31;
        const uint4 vh = Hg[c * 64 + half * 32 + q];
        const uint4 vl = Lg[c * 64 + half * 32 + q];
        *reinterpret_cast<uint4*>(&Whi_sh[c * PW + q * 8]) = vh;
        *reinterpret_cast<uint4*>(&Wlo_sh[c * PW + q * 8]) = vl;
    }

    CP_WAIT0();
    __syncthreads();                        // nat + W_sh visible

    // ---- Convert/transpose fp32 [p][a] -> bf16 xTp [p][a] pitch 24 ---------
    // LDS.128: consecutive lanes -> consecutive 16B, conflict-free.
    {
        const float4* n4 = reinterpret_cast<const float4*>(nat);
        #pragma unroll
        for (int it = 0; it < 5; ++it) {
            const int i = tid + it * 256;    // < 1280
            const float4 v = n4[i];
            const int p  = i / 5;
            const int a0 = (i - p * 5) * 4;
            __nv_bfloat162 u0 = __floats2bfloat162_rn(v.x, v.y);
            __nv_bfloat162 u1 = __floats2bfloat162_rn(v.z, v.w);
            uint2 pk;
            pk.x = *reinterpret_cast<unsigned*>(&u0);
            pk.y = *reinterpret_cast<unsigned*>(&u1);
            *reinterpret_cast<uint2*>(&xTp[p * PA + a0]) = pk;
        }
    }
    __syncthreads();                        // xTp ready; nat now dead

    // ---- Tensor-core GEMM: warp w owns K slice [32w, 32w+32) ---------------
    const int kbase = w * 32;
    const int r8 = lane & 7;
    const int g4 = lane >> 3;
    const unsigned xb = (unsigned)__cvta_generic_to_shared(xTp);
    const unsigned hb = (unsigned)__cvta_generic_to_shared(Whi_sh);
    const unsigned lb = (unsigned)__cvta_generic_to_shared(Wlo_sh);

    float C0[4] = {0.f, 0.f, 0.f, 0.f};
    float C1[4] = {0.f, 0.f, 0.f, 0.f};

    const unsigned aoff = (unsigned)((g4 & 1) << 4);
    const unsigned bco  = (unsigned)((lane & 7) * (PW * 2) + ((g4 & 1) << 4));

    #pragma unroll
    for (int kk = 0; kk < 32; kk += 16) {
        const int k = kbase + kk;
        const unsigned arow =
            xb + (unsigned)((k + ((g4 >> 1) << 3) + r8) * (PA * 2)) + aoff;
        unsigned A0[4], A1[4];
        LDSM_X4_T(A0, arow);           // M-tile 0: a cols 0-15
        LDSM_X4_T(A1, arow + 32u);     // M-tile 1: a cols 16-31 (20-31 pad)
        const unsigned bb = (unsigned)(k * 2) + bco;
        unsigned Bh[2], Bl[2];
        LDSM_X2(Bh, hb + bb);
        LDSM_X2(Bl, lb + bb);
        MMA_BF16(C0, A0, Bh);
        MMA_BF16(C0, A0, Bl);          // W = hi + lo, same accumulator
        MMA_BF16(C1, A1, Bh);
        MMA_BF16(C1, A1, Bl);
    }

    // ---- Park per-warp partials (into aliased nat region) ------------------
    {
        const int q2 = (lane & 3) * 2, tr = lane >> 2;
        *reinterpret_cast<float2*>(&Dp[w][tr     ][q2]) = make_float2(C0[0], C0[1]);
        *reinterpret_cast<float2*>(&Dp[w][tr +  8][q2]) = make_float2(C0[2], C0[3]);
        *reinterpret_cast<float2*>(&Dp[w][tr + 16][q2]) = make_float2(C1[0], C1[1]);
        *reinterpret_cast<float2*>(&Dp[w][tr + 24][q2]) = make_float2(C1[2], C1[3]);
    }
    __syncthreads();

    if (tid < AA * CCH) {
        const int a = tid >> 3, c = tid & 7;
        float sum = 0.f;
        #pragma unroll
        for (int ww = 0; ww < 8; ++ww) sum += Dp[ww][a][c];
        g_sh[a][c] = sum;
    }
    __syncthreads();

    // out[b,i,c] += sum_a U[a][i] * g[a][c]   (2 halves combine via atomics)
    if (tid < AA * CCH) {
        const int i = tid >> 3;
        const int c = tid & 7;
        float r = 0.f;
        #pragma unroll
        for (int a = 0; a < AA; ++a)
            r += __ldg(&g_U[a * AA + i]) * g_sh[a][c];
        atomicAdd(&out[(size_t)b * (AA * CCH) + tid], r);
    }
}

// ---------------------------------------------------------------------------
extern "C" void kernel_launch(void* const* d_in, const int* in_sizes, int n_in,
                              void* d_out, int out_size) {
    const float* x       = (const float*)d_in[0];
    const float* lpm     = (const float*)d_in[2];
    const float* pm      = (const float*)d_in[3];
    const float* w_first = (const float*)d_in[4];
    const float* w_rest  = (const float*)d_in[5];
    float* out = (float*)d_out;

    // Primary: precompute W hi/lo + U, zero out; triggers PDL at entry.
    precompute_kernel<<<CCH + 1 + 160, 256>>>(lpm, pm, w_first, w_rest, out);

    // Secondary: PDL launch — begins (cp.async x) while primary still runs.
    cudaLaunchConfig_t cfg = {};
    cfg.gridDim  = dim3(BSEQ * 2, 1, 1);
    cfg.blockDim = dim3(256, 1, 1);
    cfg.dynamicSmemBytes = 0;
    cfg.stream = 0;
    cudaLaunchAttribute attrs[1];
    attrs[0].id = cudaLaunchAttributeProgrammaticStreamSerialization;
    attrs[0].val.programmaticStreamSerializationAllowed = 1;
    cfg.attrs = attrs;
    cfg.numAttrs = 1;
    cudaLaunchKernelEx(&cfg, main_kernel, x, (float*)d_out);
}